// round 13
// baseline (speedup 1.0000x reference)
#include <cuda_runtime.h>
#include <cuda_fp16.h>
#include <cstdint>

#define BS    32
#define EMB   512
#define GL    256
#define WFLAT 36864
#define HIN   96
#define HOUT  94
#define NPIX  9216

typedef unsigned long long u64;
typedef unsigned int u32;

// hdn in B-fragment order: [ks(16)][nt(4)][lane(32)][reg(2)][half(2)] fp16, 16KB
__device__ __align__(16) __half g_hdnF[8192];
// conv B fp16 fragment order: [s][kk][ks(4)][ntp(4)][lane(32)][ntl(2)][reg(2)][half(2)]
__device__ __align__(16) __half g_wB[BS * WFLAT];
// x pre-converted: [s(32)][icpair(32)][px(9216)] half2 (lo=ic even, hi=ic odd) + pad
__device__ __align__(16) half2 g_x16[32 * 32 * NPIX + 128];

// ---- helpers ----------------------------------------------------------------
__device__ __forceinline__ u32 smem_u32(const void* p) {
    u32 a; asm("{ .reg .u64 t; cvta.to.shared.u64 t, %1; cvt.u32.u64 %0, t; }" : "=r"(a) : "l"(p));
    return a;
}
__device__ __forceinline__ void cpa16(u32 dst, const void* src) {
    asm volatile("cp.async.cg.shared.global [%0], [%1], 16;" :: "r"(dst), "l"(src));
}
#define CPA_COMMIT() asm volatile("cp.async.commit_group;" ::: "memory")
#define CPA_WAIT(N)  asm volatile("cp.async.wait_group %0;" :: "n"(N) : "memory")

__device__ __forceinline__ void mma16(float* c, u32 a0, u32 a1, u32 a2, u32 a3,
                                      u32 b0, u32 b1) {
    asm("mma.sync.aligned.m16n8k16.row.col.f32.f16.f16.f32 "
        "{%0,%1,%2,%3}, {%4,%5,%6,%7}, {%8,%9}, {%0,%1,%2,%3};"
        : "+f"(c[0]), "+f"(c[1]), "+f"(c[2]), "+f"(c[3])
        : "r"(a0), "r"(a1), "r"(a2), "r"(a3), "r"(b0), "r"(b1));
}

// ---------------------------------------------------------------------------
// hyper1 + xcvt fused. Blocks 0-255: hdn GEMM -> fp16 B-fragment order.
// Blocks 256-831: convert x to g_x16 (icpair-interleaved half2), riding the
// bandwidth idle under hyper1's latency-bound GEMM.
// ---------------------------------------------------------------------------
__global__ __launch_bounds__(256) void hyper1(const float* __restrict__ emb,
                                              const float* __restrict__ x,
                                              const float* __restrict__ w1w,
                                              const float* __restrict__ w1b) {
    const int tid = threadIdx.x;
    if (blockIdx.x >= 256) {
        // ---- xcvt: 2,359,296 uint4 over 576 blocks x 256 thr x 16 ----
        const int base = (blockIdx.x - 256) * 256 + tid;   // 0..147455
        const int r0 = base / 2304, c0 = base - r0 * 2304; // r=s*32+ip, c=float4 col
        const float4* xf4 = (const float4*)x;
        uint4* of4 = (uint4*)g_x16;
#pragma unroll
        for (int i = 0; i < 16; i++) {
            const int r = r0 + 64 * i;
            const float4 v0 = xf4[(size_t)(2 * r) * 2304 + c0];
            const float4 v1 = xf4[(size_t)(2 * r + 1) * 2304 + c0];
            half2 h[4];
            h[0] = __floats2half2_rn(v0.x, v1.x);
            h[1] = __floats2half2_rn(v0.y, v1.y);
            h[2] = __floats2half2_rn(v0.z, v1.z);
            h[3] = __floats2half2_rn(v0.w, v1.w);
            of4[(size_t)base + (size_t)i * 147456] = *(const uint4*)h;
        }
        return;
    }

    __shared__ float red[2][16][17];
    __shared__ __align__(16) float semb[2 * EMB];
    const int sp = blockIdx.x >> 4, jg = blockIdx.x & 15;
    const int jl = tid & 15, slice = tid >> 4;
    const int j = jg * 16 + jl;
    const int s0 = sp * 2;

    ((float4*)semb)[tid] = ((const float4*)(emb + (size_t)s0 * EMB))[tid];
    __syncthreads();

    const float4* wr = (const float4*)(w1w + (size_t)j * EMB + slice * 32);
    const float4* e0 = (const float4*)(semb + slice * 32);
    const float4* e1 = (const float4*)(semb + EMB + slice * 32);
    float a0 = 0.f, a1 = 0.f;
#pragma unroll
    for (int k = 0; k < 8; k++) {
        const float4 w = wr[k];
        const float4 x0 = e0[k], x1 = e1[k];
        a0 += w.x * x0.x + w.y * x0.y + w.z * x0.z + w.w * x0.w;
        a1 += w.x * x1.x + w.y * x1.y + w.z * x1.z + w.w * x1.w;
    }
    red[0][slice][jl] = a0;
    red[1][slice][jl] = a1;
    __syncthreads();
    if (tid < 32) {
        const int si = tid >> 4, l = tid & 15;
        float a = 0.f;
#pragma unroll
        for (int t = 0; t < 16; t++) a += red[si][t][l];
        const int jj = jg * 16 + l;
        a += w1b[jj];
        a = a > 0.f ? a : 0.f;
        const int s = s0 + si;
        const int ks = jj >> 4, kpos = jj & 15;
        const int reg = kpos >> 3, klo = kpos & 7;
        const int lanef = (s & 7) * 4 + (klo >> 1);
        const int hsel = klo & 1;
        const int nt = s >> 3;
        g_hdnF[((ks * 4 + nt) * 32 + lanef) * 4 + reg * 2 + hsel] = __float2half_rn(a);
    }
}

// ---------------------------------------------------------------------------
// hyper2: weight GEMM on tensor cores (R11 verbatim).
// ---------------------------------------------------------------------------
#define H2STR 72   // half2 units per kpair row (72 % 32 == 8 -> bijective banks)

__global__ __launch_bounds__(128) void hyper2(const float* __restrict__ w2w,
                                              const float* __restrict__ w2b) {
    __shared__ __align__(16) __half sH[8192];
    __shared__ __align__(16) half2 sW[32 * H2STR];

    const int tid = threadIdx.x;
    const int lane = tid & 31, wrp = tid >> 5;
    const int r0 = blockIdx.x * 64;

    const u32 sHu = smem_u32(sH);
#pragma unroll
    for (int i = 0; i < 8; i++)
        cpa16(sHu + (u32)((i * 128 + tid) * 16), (const char*)g_hdnF + (i * 128 + tid) * 16);
    CPA_COMMIT();

    float acc[4][4];
#pragma unroll
    for (int nt = 0; nt < 4; nt++)
#pragma unroll
        for (int r = 0; r < 4; r++) acc[nt][r] = 0.f;

    const int mbase = wrp * 16 + (lane >> 2);
    bool hwaited = false;

#pragma unroll 1
    for (int kc = 0; kc < 4; kc++) {
        __syncthreads();
#pragma unroll
        for (int it = 0; it < 8; it++) {
            const int idx = it * 128 + tid;
            const int r = idx >> 4, k4 = idx & 15;
            const float4 v = *(const float4*)&w2w[(size_t)(r0 + r) * GL + kc * 64 + k4 * 4];
            sW[(2 * k4 + 0) * H2STR + r] = __floats2half2_rn(v.x, v.y);
            sW[(2 * k4 + 1) * H2STR + r] = __floats2half2_rn(v.z, v.w);
        }
        if (!hwaited) { CPA_WAIT(0); hwaited = true; }
        __syncthreads();

#pragma unroll
        for (int ks = 0; ks < 4; ks++) {
            const int ksg = kc * 4 + ks;
            const int ar = (ks * 8 + (lane & 3)) * H2STR + mbase;
            const u32 a0 = *(const u32*)&sW[ar];
            const u32 a1 = *(const u32*)&sW[ar + 8];
            const u32 a2 = *(const u32*)&sW[ar + 4 * H2STR];
            const u32 a3 = *(const u32*)&sW[ar + 4 * H2STR + 8];
#pragma unroll
            for (int nt = 0; nt < 4; nt++) {
                const uint2 bv = *(const uint2*)&sH[((ksg * 4 + nt) * 32 + lane) * 4];
                mma16(acc[nt], a0, a1, a2, a3, bv.x, bv.y);
            }
        }
    }

    const int row0 = r0 + wrp * 16 + (lane >> 2);
    const int row1 = row0 + 8;
    int  frg[2];
    float bias[2];
#pragma unroll
    for (int i = 0; i < 2; i++) {
        const int row = i ? row1 : row0;
        const int oc  = row / 576;
        const int rem = row - oc * 576;
        const int ic  = rem / 9;
        const int kk  = rem - ic * 9;
        const int ks = ic >> 4, kpos = ic & 15;
        const int reg = kpos >> 3, klo = kpos & 7;
        const int lanef = (oc & 7) * 4 + (klo >> 1);
        const int hsel = klo & 1;
        const int nt2 = oc >> 3, ntp = nt2 >> 1, ntl = nt2 & 1;
        frg[i] = (((kk * 4 + ks) * 4 + ntp) * 32 + lanef) * 8 + ntl * 4 + reg * 2 + hsel;
        bias[i] = w2b[row];
    }
#pragma unroll
    for (int nt = 0; nt < 4; nt++) {
        const int sA = nt * 8 + (lane & 3) * 2;
        g_wB[(size_t)(sA + 0) * WFLAT + frg[0]] = __float2half_rn(acc[nt][0] + bias[0]);
        g_wB[(size_t)(sA + 1) * WFLAT + frg[0]] = __float2half_rn(acc[nt][1] + bias[0]);
        g_wB[(size_t)(sA + 0) * WFLAT + frg[1]] = __float2half_rn(acc[nt][2] + bias[1]);
        g_wB[(size_t)(sA + 1) * WFLAT + frg[1]] = __float2half_rn(acc[nt][3] + bias[1]);
    }
}

// ---------------------------------------------------------------------------
// convk: R11 compute protocol; A staged via pure cp.async from g_x16
// (81 x 16B chunks per icpair row). No launch-bounds hint.
// ---------------------------------------------------------------------------
#define ASTR 328                              // half2 units per icpair row
#define SMA_BYTES (32 * ASTR * 4)             // 41984
#define SMEM_REQ  (SMA_BYTES + 2 * 8192)      // 58368

__global__ __launch_bounds__(128) void convk(float* __restrict__ out) {
    extern __shared__ char S[];
    half2*  sA = (half2*)S;
    __half* sB = (__half*)(S + SMA_BYTES);
    const u32 sAu = smem_u32(S);
    const u32 sBu = sAu + SMA_BYTES;

    const int tid  = threadIdx.x;
    const int lane = tid & 31, wrp = tid >> 5;
    const int s    = blockIdx.y;
    const int p0   = blockIdx.x * 128;
    const __half* gB0 = g_wB + (size_t)s * WFLAT;

    // ---- prefetch B kk=0 (group 0) ----
#pragma unroll
    for (int i = 0; i < 4; i++)
        cpa16(sBu + (u32)((i * 128 + tid) * 16), (const char*)gB0 + (i * 128 + tid) * 16);
    CPA_COMMIT();

    // ---- stage A via cp.async (group 1): 32 rows x 81 chunks of 16B ----
    {
        const char* gx = (const char*)(g_x16 + ((size_t)s * 32) * NPIX + p0);
#pragma unroll
        for (int rr = 0; rr < 8; rr++) {
            const int ip = wrp * 8 + rr;
            const char* src = gx + (size_t)ip * (NPIX * 4);
            const u32 dst = sAu + (u32)(ip * (ASTR * 4));
#pragma unroll
            for (int i = 0; i < 3; i++) {
                const int c = i * 32 + lane;
                if (c < 81) cpa16(dst + (u32)(c * 16), src + c * 16);
            }
        }
    }
    CPA_COMMIT();

    float acc[2][8][4];
#pragma unroll
    for (int mt = 0; mt < 2; mt++)
#pragma unroll
        for (int nt = 0; nt < 8; nt++)
#pragma unroll
            for (int r = 0; r < 4; r++) acc[mt][nt][r] = 0.f;

    const int pxb = wrp * 32 + (lane >> 2);

#pragma unroll 1
    for (int kk = 0; kk < 9; kk++) {
        if (kk < 8) {   // prefetch kk+1 into other buffer
            const char* src = (const char*)(gB0 + (size_t)(kk + 1) * 4096);
            const u32 dst = sBu + (u32)(((kk + 1) & 1) * 8192);
#pragma unroll
            for (int i = 0; i < 4; i++)
                cpa16(dst + (u32)((i * 128 + tid) * 16), src + (i * 128 + tid) * 16);
            CPA_COMMIT();
            CPA_WAIT(1);    // kk=0: waits B0 + A; kk>0: waits B(kk)
        } else {
            CPA_WAIT(0);
        }
        __syncthreads();

        const int off = (kk / 3) * 96 + (kk % 3);
        const __half* B = sB + (kk & 1) * 4096;

#pragma unroll
        for (int ks = 0; ks < 4; ks++) {
            u32 b0[8], b1[8];
#pragma unroll
            for (int ntp = 0; ntp < 4; ntp++) {
                const uint4 bv = *(const uint4*)&B[((ks * 4 + ntp) * 32 + lane) * 8];
                b0[2 * ntp + 0] = bv.x; b1[2 * ntp + 0] = bv.y;
                b0[2 * ntp + 1] = bv.z; b1[2 * ntp + 1] = bv.w;
            }
#pragma unroll
            for (int mt = 0; mt < 2; mt++) {
                const int a = (ks * 8 + (lane & 3)) * ASTR + pxb + mt * 16 + off;
                const u32 a0 = *(const u32*)&sA[a];
                const u32 a1 = *(const u32*)&sA[a + 8];
                const u32 a2 = *(const u32*)&sA[a + 4 * ASTR];
                const u32 a3 = *(const u32*)&sA[a + 4 * ASTR + 8];
#pragma unroll
                for (int nt = 0; nt < 8; nt++)
                    mma16(acc[mt][nt], a0, a1, a2, a3, b0[nt], b1[nt]);
            }
        }
        __syncthreads();
    }

    // ---- epilogue: D[px][oc]; mask h,w >= 94 ----
    const int oc0 = (lane & 3) * 2;
#pragma unroll
    for (int mt = 0; mt < 2; mt++) {
#pragma unroll
        for (int hf = 0; hf < 2; hf++) {
            const int px = p0 + pxb + mt * 16 + hf * 8;
            const int h = px / 96, w = px - h * 96;
            if (h < HOUT && w < HOUT) {
                float* op = out + ((size_t)s * 64) * 8836 + h * 94 + w;
#pragma unroll
                for (int nt = 0; nt < 8; nt++) {
                    op[(nt * 8 + oc0 + 0) * 8836] = acc[mt][nt][hf * 2 + 0];
                    op[(nt * 8 + oc0 + 1) * 8836] = acc[mt][nt][hf * 2 + 1];
                }
            }
        }
    }
}

// ---------------------------------------------------------------------------
extern "C" void kernel_launch(void* const* d_in, const int* in_sizes, int n_in,
                              void* d_out, int out_size) {
    const float* emb = (const float*)d_in[0];
    const float* x   = (const float*)d_in[1];
    const float* w1w = (const float*)d_in[2];
    const float* w1b = (const float*)d_in[3];
    const float* w2w = (const float*)d_in[4];
    const float* w2b = (const float*)d_in[5];
    float* out = (float*)d_out;

    cudaFuncSetAttribute(convk, cudaFuncAttributeMaxDynamicSharedMemorySize, SMEM_REQ);

    hyper1<<<832, 256>>>(emb, x, w1w, w1b);   // 256 hdn blocks + 576 xcvt blocks
    hyper2<<<WFLAT / 64, 128>>>(w2w, w2b);
    // tile 71 (px >= 9088) is entirely h >= 94 -> dropped
    convk<<<dim3(71, 32), 128, SMEM_REQ>>>(out);
}

// round 14
// speedup vs baseline: 1.1016x; 1.1016x over previous
#include <cuda_runtime.h>
#include <cuda_fp16.h>
#include <cstdint>

#define BS    32
#define EMB   512
#define GL    256
#define WFLAT 36864
#define HIN   96
#define HOUT  94
#define NPIX  9216
#define XCLAMP (32u*64u*9216u - 4u)

typedef unsigned long long u64;
typedef unsigned int u32;

// hdn in B-fragment order: [ks(16)][nt(4)][lane(32)][reg(2)][half(2)] fp16, 16KB
__device__ __align__(16) __half g_hdnF[8192];
// conv B fp16 fragment order: [s][kk][ks(4)][ntp(4)][lane(32)][ntl(2)][reg(2)][half(2)]
__device__ __align__(16) __half g_wB[BS * WFLAT];

// ---- helpers ----------------------------------------------------------------
__device__ __forceinline__ u32 smem_u32(const void* p) {
    u32 a; asm("{ .reg .u64 t; cvta.to.shared.u64 t, %1; cvt.u32.u64 %0, t; }" : "=r"(a) : "l"(p));
    return a;
}
__device__ __forceinline__ void cpa16(u32 dst, const void* src) {
    asm volatile("cp.async.cg.shared.global [%0], [%1], 16;" :: "r"(dst), "l"(src));
}
#define CPA_COMMIT() asm volatile("cp.async.commit_group;" ::: "memory")
#define CPA_WAIT(N)  asm volatile("cp.async.wait_group %0;" :: "n"(N) : "memory")

__device__ __forceinline__ void mma16(float* c, u32 a0, u32 a1, u32 a2, u32 a3,
                                      u32 b0, u32 b1) {
    asm("mma.sync.aligned.m16n8k16.row.col.f32.f16.f16.f32 "
        "{%0,%1,%2,%3}, {%4,%5,%6,%7}, {%8,%9}, {%0,%1,%2,%3};"
        : "+f"(c[0]), "+f"(c[1]), "+f"(c[2]), "+f"(c[3])
        : "r"(a0), "r"(a1), "r"(a2), "r"(a3), "r"(b0), "r"(b1));
}

// ---------------------------------------------------------------------------
// hyper1 (R12 standalone, measured 6.88us): hdn -> fp16 B-fragment order.
// grid = 256 (16 sample-pairs x 16 j-groups of 16), block 256 = 16 j x 16 k.
// emb staged once through smem.
// ---------------------------------------------------------------------------
__global__ __launch_bounds__(256) void hyper1(const float* __restrict__ emb,
                                              const float* __restrict__ w1w,
                                              const float* __restrict__ w1b) {
    __shared__ float red[2][16][17];
    __shared__ __align__(16) float semb[2 * EMB];
    const int tid = threadIdx.x;
    const int sp = blockIdx.x >> 4, jg = blockIdx.x & 15;
    const int jl = tid & 15, slice = tid >> 4;
    const int j = jg * 16 + jl;
    const int s0 = sp * 2;

    ((float4*)semb)[tid] = ((const float4*)(emb + (size_t)s0 * EMB))[tid];
    __syncthreads();

    const float4* wr = (const float4*)(w1w + (size_t)j * EMB + slice * 32);
    const float4* e0 = (const float4*)(semb + slice * 32);
    const float4* e1 = (const float4*)(semb + EMB + slice * 32);
    float a0 = 0.f, a1 = 0.f;
#pragma unroll
    for (int k = 0; k < 8; k++) {
        const float4 w = wr[k];
        const float4 x0 = e0[k], x1 = e1[k];
        a0 += w.x * x0.x + w.y * x0.y + w.z * x0.z + w.w * x0.w;
        a1 += w.x * x1.x + w.y * x1.y + w.z * x1.z + w.w * x1.w;
    }
    red[0][slice][jl] = a0;
    red[1][slice][jl] = a1;
    __syncthreads();
    if (tid < 32) {
        const int si = tid >> 4, l = tid & 15;
        float a = 0.f;
#pragma unroll
        for (int t = 0; t < 16; t++) a += red[si][t][l];
        const int jj = jg * 16 + l;
        a += w1b[jj];
        a = a > 0.f ? a : 0.f;
        const int s = s0 + si;
        const int ks = jj >> 4, kpos = jj & 15;
        const int reg = kpos >> 3, klo = kpos & 7;
        const int lanef = (s & 7) * 4 + (klo >> 1);
        const int hsel = klo & 1;
        const int nt = s >> 3;
        g_hdnF[((ks * 4 + nt) * 32 + lanef) * 4 + reg * 2 + hsel] = __float2half_rn(a);
    }
}

// ---------------------------------------------------------------------------
// hyper2: weight GEMM on tensor cores (R11 verbatim).
// ---------------------------------------------------------------------------
#define H2STR 72   // half2 units per kpair row (72 % 32 == 8 -> bijective banks)

__global__ __launch_bounds__(128) void hyper2(const float* __restrict__ w2w,
                                              const float* __restrict__ w2b) {
    __shared__ __align__(16) __half sH[8192];
    __shared__ __align__(16) half2 sW[32 * H2STR];

    const int tid = threadIdx.x;
    const int lane = tid & 31, wrp = tid >> 5;
    const int r0 = blockIdx.x * 64;

    const u32 sHu = smem_u32(sH);
#pragma unroll
    for (int i = 0; i < 8; i++)
        cpa16(sHu + (u32)((i * 128 + tid) * 16), (const char*)g_hdnF + (i * 128 + tid) * 16);
    CPA_COMMIT();

    float acc[4][4];
#pragma unroll
    for (int nt = 0; nt < 4; nt++)
#pragma unroll
        for (int r = 0; r < 4; r++) acc[nt][r] = 0.f;

    const int mbase = wrp * 16 + (lane >> 2);
    bool hwaited = false;

#pragma unroll 1
    for (int kc = 0; kc < 4; kc++) {
        __syncthreads();
#pragma unroll
        for (int it = 0; it < 8; it++) {
            const int idx = it * 128 + tid;
            const int r = idx >> 4, k4 = idx & 15;
            const float4 v = *(const float4*)&w2w[(size_t)(r0 + r) * GL + kc * 64 + k4 * 4];
            sW[(2 * k4 + 0) * H2STR + r] = __floats2half2_rn(v.x, v.y);
            sW[(2 * k4 + 1) * H2STR + r] = __floats2half2_rn(v.z, v.w);
        }
        if (!hwaited) { CPA_WAIT(0); hwaited = true; }
        __syncthreads();

#pragma unroll
        for (int ks = 0; ks < 4; ks++) {
            const int ksg = kc * 4 + ks;
            const int ar = (ks * 8 + (lane & 3)) * H2STR + mbase;
            const u32 a0 = *(const u32*)&sW[ar];
            const u32 a1 = *(const u32*)&sW[ar + 8];
            const u32 a2 = *(const u32*)&sW[ar + 4 * H2STR];
            const u32 a3 = *(const u32*)&sW[ar + 4 * H2STR + 8];
#pragma unroll
            for (int nt = 0; nt < 4; nt++) {
                const uint2 bv = *(const uint2*)&sH[((ksg * 4 + nt) * 32 + lane) * 4];
                mma16(acc[nt], a0, a1, a2, a3, bv.x, bv.y);
            }
        }
    }

    const int row0 = r0 + wrp * 16 + (lane >> 2);
    const int row1 = row0 + 8;
    int  frg[2];
    float bias[2];
#pragma unroll
    for (int i = 0; i < 2; i++) {
        const int row = i ? row1 : row0;
        const int oc  = row / 576;
        const int rem = row - oc * 576;
        const int ic  = rem / 9;
        const int kk  = rem - ic * 9;
        const int ks = ic >> 4, kpos = ic & 15;
        const int reg = kpos >> 3, klo = kpos & 7;
        const int lanef = (oc & 7) * 4 + (klo >> 1);
        const int hsel = klo & 1;
        const int nt2 = oc >> 3, ntp = nt2 >> 1, ntl = nt2 & 1;
        frg[i] = (((kk * 4 + ks) * 4 + ntp) * 32 + lanef) * 8 + ntl * 4 + reg * 2 + hsel;
        bias[i] = w2b[row];
    }
#pragma unroll
    for (int nt = 0; nt < 4; nt++) {
        const int sA = nt * 8 + (lane & 3) * 2;
        g_wB[(size_t)(sA + 0) * WFLAT + frg[0]] = __float2half_rn(acc[nt][0] + bias[0]);
        g_wB[(size_t)(sA + 1) * WFLAT + frg[0]] = __float2half_rn(acc[nt][1] + bias[0]);
        g_wB[(size_t)(sA + 0) * WFLAT + frg[1]] = __float2half_rn(acc[nt][2] + bias[1]);
        g_wB[(size_t)(sA + 1) * WFLAT + frg[1]] = __float2half_rn(acc[nt][3] + bias[1]);
    }
}

// ---------------------------------------------------------------------------
// convk: R11 verbatim (the 97.3us config). fp16 mma.sync implicit GEMM.
// 128 px x 64 oc per CTA; A slab LDG-staged once; B double-buffered cp.async.
// ---------------------------------------------------------------------------
#define ASTR 328                              // half2 units per icpair row
#define SMA_BYTES (32 * ASTR * 4)             // 41984
#define SMEM_REQ  (SMA_BYTES + 2 * 8192)      // 58368

__global__ __launch_bounds__(128) void convk(const float* __restrict__ x,
                                             float* __restrict__ out) {
    extern __shared__ char S[];
    half2*  sA = (half2*)S;
    __half* sB = (__half*)(S + SMA_BYTES);
    const u32 sBu = smem_u32(S) + SMA_BYTES;

    const int tid  = threadIdx.x;
    const int lane = tid & 31, wrp = tid >> 5;
    const int s    = blockIdx.y;
    const int p0   = blockIdx.x * 128;
    const u32 xs0  = (u32)s * (64u * NPIX);
    const __half* gB0 = g_wB + (size_t)s * WFLAT;

    // ---- prefetch B kk=0 (rides under the A LDG burst) ----
#pragma unroll
    for (int i = 0; i < 4; i++)
        cpa16(sBu + (u32)((i * 128 + tid) * 16), (const char*)gB0 + (i * 128 + tid) * 16);
    CPA_COMMIT();

    // ---- stage A: 32 icpairs x 322 px, fully unrolled (MLP ~24 LDG/thread) ----
#pragma unroll
    for (int ipl = 0; ipl < 8; ipl++) {
        const int ip  = wrp * 8 + ipl;
        const u32 r0b = xs0 + (u32)(2 * ip) * NPIX + (u32)p0;
#pragma unroll
        for (int c = 0; c < 3; c++) {
            const int px = c * 128 + lane * 4;
            u32 i0 = r0b + (u32)px;          if (i0 > XCLAMP) i0 = XCLAMP;
            u32 i1 = r0b + NPIX + (u32)px;   if (i1 > XCLAMP) i1 = XCLAMP;
            const float4 v0 = *(const float4*)(x + i0);
            const float4 v1 = *(const float4*)(x + i1);
            if (px < 326) {
                half2 h[4];
                h[0] = __floats2half2_rn(v0.x, v1.x);
                h[1] = __floats2half2_rn(v0.y, v1.y);
                h[2] = __floats2half2_rn(v0.z, v1.z);
                h[3] = __floats2half2_rn(v0.w, v1.w);
                *(uint4*)&sA[ip * ASTR + px] = *(const uint4*)h;
            }
        }
    }

    float acc[2][8][4];
#pragma unroll
    for (int mt = 0; mt < 2; mt++)
#pragma unroll
        for (int nt = 0; nt < 8; nt++)
#pragma unroll
            for (int r = 0; r < 4; r++) acc[mt][nt][r] = 0.f;

    const int pxb = wrp * 32 + (lane >> 2);

#pragma unroll 1
    for (int kk = 0; kk < 9; kk++) {
        if (kk < 8) {   // prefetch kk+1 into other buffer
            const char* src = (const char*)(gB0 + (size_t)(kk + 1) * 4096);
            const u32 dst = sBu + (u32)(((kk + 1) & 1) * 8192);
#pragma unroll
            for (int i = 0; i < 4; i++)
                cpa16(dst + (u32)((i * 128 + tid) * 16), src + (i * 128 + tid) * 16);
            CPA_COMMIT();
            CPA_WAIT(1);
        } else {
            CPA_WAIT(0);
        }
        __syncthreads();

        const int off = (kk / 3) * 96 + (kk % 3);
        const __half* B = sB + (kk & 1) * 4096;

#pragma unroll
        for (int ks = 0; ks < 4; ks++) {
            u32 b0[8], b1[8];
#pragma unroll
            for (int ntp = 0; ntp < 4; ntp++) {
                const uint4 bv = *(const uint4*)&B[((ks * 4 + ntp) * 32 + lane) * 8];
                b0[2 * ntp + 0] = bv.x; b1[2 * ntp + 0] = bv.y;
                b0[2 * ntp + 1] = bv.z; b1[2 * ntp + 1] = bv.w;
            }
#pragma unroll
            for (int mt = 0; mt < 2; mt++) {
                const int a = (ks * 8 + (lane & 3)) * ASTR + pxb + mt * 16 + off;
                const u32 a0 = *(const u32*)&sA[a];
                const u32 a1 = *(const u32*)&sA[a + 8];
                const u32 a2 = *(const u32*)&sA[a + 4 * ASTR];
                const u32 a3 = *(const u32*)&sA[a + 4 * ASTR + 8];
#pragma unroll
                for (int nt = 0; nt < 8; nt++)
                    mma16(acc[mt][nt], a0, a1, a2, a3, b0[nt], b1[nt]);
            }
        }
        __syncthreads();
    }

    // ---- epilogue: D[px][oc]; mask h,w >= 94 ----
    const int oc0 = (lane & 3) * 2;
#pragma unroll
    for (int mt = 0; mt < 2; mt++) {
#pragma unroll
        for (int hf = 0; hf < 2; hf++) {
            const int px = p0 + pxb + mt * 16 + hf * 8;
            const int h = px / 96, w = px - h * 96;
            if (h < HOUT && w < HOUT) {
                float* op = out + ((size_t)s * 64) * 8836 + h * 94 + w;
#pragma unroll
                for (int nt = 0; nt < 8; nt++) {
                    op[(nt * 8 + oc0 + 0) * 8836] = acc[mt][nt][hf * 2 + 0];
                    op[(nt * 8 + oc0 + 1) * 8836] = acc[mt][nt][hf * 2 + 1];
                }
            }
        }
    }
}

// ---------------------------------------------------------------------------
extern "C" void kernel_launch(void* const* d_in, const int* in_sizes, int n_in,
                              void* d_out, int out_size) {
    const float* emb = (const float*)d_in[0];
    const float* x   = (const float*)d_in[1];
    const float* w1w = (const float*)d_in[2];
    const float* w1b = (const float*)d_in[3];
    const float* w2w = (const float*)d_in[4];
    const float* w2b = (const float*)d_in[5];
    float* out = (float*)d_out;

    cudaFuncSetAttribute(convk, cudaFuncAttributeMaxDynamicSharedMemorySize, SMEM_REQ);

    hyper1<<<256, 256>>>(emb, w1w, w1b);
    hyper2<<<WFLAT / 64, 128>>>(w2w, w2b);
    // tile 71 (px >= 9088) is entirely h >= 94 -> dropped
    convk<<<dim3(71, 32), 128, SMEM_REQ>>>(x, out);
}